// round 13
// baseline (speedup 1.0000x reference)
#include <cuda_runtime.h>
#include <cuda_bf16.h>
#include <math.h>
#include <stdint.h>

#define B_  4
#define C_  64
#define HH  128
#define WW  128
#define F_  5
#define L_  512
#define NH_ 128

// ---------------- device scratch ----------------
__device__ float g_mu[B_*F_*L_];
__device__ unsigned char g_rmap[B_*HH*WW];
__device__ float g_Tg[B_*9*F_*C_];               // [b][tap][f][c]
__device__ float g_Tb[B_*9*F_*C_];
__device__ __nv_bfloat16 g_act[(size_t)B_*HH*WW*NH_];  // NHWC bf16
__device__ __nv_bfloat16 g_Aw[9*128*128];        // [tap][c128][nh] bf16
__device__ float g_mean[B_*C_];
__device__ float g_rsig[B_*C_];
__device__ float g_pre[(size_t)B_*HH*WW*128];    // blended avg+biases [b][y][x][m]

// ---------------- helpers ----------------
__device__ __forceinline__ uint32_t smem_u32(const void* p) {
    uint32_t a;
    asm("{ .reg .u64 t; cvta.to.shared.u64 t, %1; cvt.u32.u64 %0, t; }" : "=r"(a) : "l"(p));
    return a;
}
__device__ __forceinline__ void cpa16(uint32_t dst, const void* src, uint32_t ssz) {
    asm volatile("cp.async.ca.shared.global [%0], [%1], 16, %2;"
                 :: "r"(dst), "l"(src), "r"(ssz) : "memory");
}
__device__ __forceinline__ void ldsm4(uint32_t* r, uint32_t addr) {
    asm volatile("ldmatrix.sync.aligned.m8n8.x4.shared.b16 {%0,%1,%2,%3}, [%4];"
        : "=r"(r[0]), "=r"(r[1]), "=r"(r[2]), "=r"(r[3]) : "r"(addr));
}
__device__ __forceinline__ void mma_bf16(float* d, const uint32_t* a, const uint32_t* b) {
    asm volatile("mma.sync.aligned.m16n8k16.row.col.f32.bf16.bf16.f32 "
        "{%0,%1,%2,%3},{%4,%5,%6,%7},{%8,%9},{%0,%1,%2,%3};"
        : "+f"(d[0]), "+f"(d[1]), "+f"(d[2]), "+f"(d[3])
        : "r"(a[0]), "r"(a[1]), "r"(a[2]), "r"(a[3]), "r"(b[0]), "r"(b[1]));
}

// ================= K1: all independent preps (mu | region | stats | wprep | sconv) =====
// grid 4416 x 256
__global__ void prep_all(const float* __restrict__ codes,
                         const float* __restrict__ fc_w,
                         const float* __restrict__ fc_b,
                         const float* __restrict__ seg,
                         const float* __restrict__ x,
                         const float* __restrict__ sgw,
                         const float* __restrict__ sbw,
                         const float* __restrict__ mask,
                         const float* __restrict__ ssw,
                         const float* __restrict__ ssb) {
    __shared__ float sh1[256], sh2[256];
    __shared__ float sw[NH_*27];
    __shared__ float smk[3][3][34];
    int bid = blockIdx.x, t = threadIdx.x;
    if (bid < 1280) {
        // mu: warp per output
        int gw = bid*8 + (t >> 5);
        int lane = t & 31;
        int bf = gw >> 9, k = gw & 511;
        int f = bf % F_;
        const float4* wp = (const float4*)(fc_w + ((size_t)f*L_ + k)*L_);
        const float4* cp = (const float4*)(codes + (size_t)bf*L_);
        float s = 0.f;
        #pragma unroll
        for (int i = 0; i < 4; ++i) {
            float4 w4 = wp[lane + i*32];
            float4 c4 = cp[lane + i*32];
            s = fmaf(w4.x, c4.x, fmaf(w4.y, c4.y, fmaf(w4.z, c4.z, fmaf(w4.w, c4.w, s))));
        }
        #pragma unroll
        for (int o = 16; o > 0; o >>= 1) s += __shfl_down_sync(0xffffffffu, s, o);
        if (lane == 0)
            g_mu[bf*L_ + k] = fmaxf(s + fc_b[f*L_ + k], 0.f);
    } else if (bid < 1536) {
        int p = (bid - 1280)*256 + t;
        int b = p >> 14, pix = p & 16383;
        int r = 5;
        #pragma unroll
        for (int j = 0; j < F_; ++j)
            if (seg[(b*F_ + j)*16384 + pix] > 0.f) r = j;
        g_rmap[p] = (unsigned char)r;
    } else if (bid < 1792) {
        int bc = bid - 1536;
        const float4* p = (const float4*)(x + (size_t)bc*16384);
        float s = 0.f, s2 = 0.f;
        for (int i = t; i < 4096; i += 256) {
            float4 v = p[i];
            s += v.x + v.y + v.z + v.w;
            s2 = fmaf(v.x, v.x, fmaf(v.y, v.y, fmaf(v.z, v.z, fmaf(v.w, v.w, s2))));
        }
        sh1[t] = s; sh2[t] = s2;
        __syncthreads();
        for (int o = 128; o > 0; o >>= 1) {
            if (t < o) { sh1[t] += sh1[t+o]; sh2[t] += sh2[t+o]; }
            __syncthreads();
        }
        if (t == 0) {
            float m = sh1[0] * (1.f/16384.f);
            float var = sh2[0] * (1.f/16384.f) - m*m;
            g_mean[bc] = m;
            g_rsig[bc] = rsqrtf(var + 1e-5f);
        }
    } else if (bid < 2368) {
        int idx = (bid - 1792)*256 + t;
        int nh = idx & 127, c = (idx >> 7) & 127, tap = idx >> 14;
        const float* src = (c < 64) ? sgw : sbw;
        float v = src[(((c & 63)*128) + nh)*9 + tap];
        g_Aw[idx] = __float2bfloat16_rn(v);
    } else {
        // sconv: mask(3) -> actv(128) bf16 NHWC
        int v = bid - 2368;
        int xblk = v & 3, y = (v >> 2) & 127, b = v >> 9;
        int x0 = xblk*32;
        for (int i = t; i < NH_*27; i += 256) sw[i] = ssw[i];
        for (int i = t; i < 3*3*34; i += 256) {
            int ch = i / 102, rem = i - ch*102;
            int r = rem / 34, cx = rem - r*34;
            int gy = y + r - 1, gx = x0 + cx - 1;
            float vv = 0.f;
            if ((unsigned)gy < 128u && (unsigned)gx < 128u)
                vv = mask[((b*3 + ch) << 14) + (gy << 7) + gx];
            smk[ch][r][cx] = vv;
        }
        __syncthreads();
        int px = t >> 3, g = t & 7;
        float mv[3][3][3];
        #pragma unroll
        for (int ch = 0; ch < 3; ++ch)
            #pragma unroll
            for (int r = 0; r < 3; ++r)
                #pragma unroll
                for (int d = 0; d < 3; ++d)
                    mv[ch][r][d] = smk[ch][r][px + d];
        int nh0 = g*16;
        unsigned hw[8];
        #pragma unroll 2
        for (int k = 0; k < 16; ++k) {
            int nh = nh0 + k;
            float acc = __ldg(&ssb[nh]);
            const float* wp = &sw[nh*27];
            #pragma unroll
            for (int ch = 0; ch < 3; ++ch)
                #pragma unroll
                for (int r = 0; r < 3; ++r)
                    #pragma unroll
                    for (int d = 0; d < 3; ++d)
                        acc = fmaf(mv[ch][r][d], wp[ch*9 + r*3 + d], acc);
            acc = fmaxf(acc, 0.f);
            unsigned hb = (unsigned)__bfloat16_as_ushort(__float2bfloat16_rn(acc));
            if (k & 1) hw[k>>1] |= hb << 16;
            else       hw[k>>1]  = hb;
        }
        size_t base = (((size_t)(b*128 + y))*128 + (x0 + px))*128 + nh0;
        uint4* dh = (uint4*)&g_act[base];
        dh[0] = make_uint4(hw[0], hw[1], hw[2], hw[3]);
        dh[1] = make_uint4(hw[4], hw[5], hw[6], hw[7]);
    }
}

// ================= K2: tables v3 — coalesced smem transpose =================
// grid 128 (tbl x 64 c), 256 thr. Stage w[c] (512x9) transposed to [tap][l],
// then warps compute (b,f) outputs with conflict-free LDS + coalesced mu LDG.
__global__ void table_kernel(const float* __restrict__ cgw,
                             const float* __restrict__ cbw) {
    __shared__ float swT[9*512];      // 18KB, [tap][l]
    int bid = blockIdx.x, t = threadIdx.x;
    int tbl = bid >> 6, c = bid & 63;
    const float* w = (tbl ? cbw : cgw) + (size_t)c*4608;
    for (int i = t; i < 4608; i += 256) {
        float v = w[i];
        int l = i / 9, tp = i - l*9;
        swT[tp*512 + l] = v;
    }
    __syncthreads();

    int warp = t >> 5, lane = t & 31;
    float* gT = tbl ? g_Tb : g_Tg;
    for (int bf = warp; bf < 20; bf += 8) {
        int b = bf / 5, f = bf - b*5;
        const float* m = g_mu + bf*L_;
        float s[9];
        #pragma unroll
        for (int tp = 0; tp < 9; ++tp) s[tp] = 0.f;
        for (int l = lane; l < 512; l += 32) {
            float mv = __ldg(&m[l]);
            #pragma unroll
            for (int tp = 0; tp < 9; ++tp)
                s[tp] = fmaf(swT[tp*512 + l], mv, s[tp]);
        }
        #pragma unroll
        for (int tp = 0; tp < 9; ++tp) {
            float v = s[tp];
            #pragma unroll
            for (int o = 16; o > 0; o >>= 1) v += __shfl_down_sync(0xffffffffu, v, o);
            if (lane == 0)
                gT[((b*9 + tp)*F_ + f)*64 + c] = v;
        }
    }
}

// ================= K3: gather v2 — conflict-free (warp=pixel, lane=4 channels) =======
// grid 256 (b x 64 row-pairs), 256 thr.
__global__ void gather_kernel(const float* __restrict__ cgb,
                              const float* __restrict__ cbb,
                              const float* __restrict__ sgb,
                              const float* __restrict__ sbb,
                              const float* __restrict__ bgam,
                              const float* __restrict__ bbet) {
    __shared__ float sT[2][54*68];       // [tbl][(tap*6+r)*68 + c]; r=5 row zero
    __shared__ unsigned short sIdx[256][10];
    int bid = blockIdx.x, t = threadIdx.x;
    int b = bid >> 6, y0 = (bid & 63)*2;

    for (int i = t; i < 54*64; i += 256) {
        int row = i >> 6, c = i & 63;
        int tp = row / 6, q = row - tp*6;
        float vg = 0.f, vb = 0.f;
        if (q < 5) {
            int src = b*2880 + (tp*5 + q)*64 + c;
            vg = g_Tg[src]; vb = g_Tb[src];
        }
        sT[0][row*68 + c] = vg;
        sT[1][row*68 + c] = vb;
    }
    {
        int y = y0 + (t >> 7), x = t & 127;
        #pragma unroll
        for (int tp = 0; tp < 9; ++tp) {
            int dy = tp / 3, dx = tp - 3*dy;
            int gy = y + dy - 1, gx = x + dx - 1;
            int rr = 5;
            if ((unsigned)gy < 128u && (unsigned)gx < 128u)
                rr = g_rmap[(b << 14) + (gy << 7) + gx];
            sIdx[t][tp] = (unsigned short)((tp*6 + rr)*68);
        }
    }
    __syncthreads();

    int warp = t >> 5, lane = t & 31;
    int c128 = lane*4;
    int half = c128 >> 6;
    int cc = c128 & 63;
    float bl = 1.f / (1.f + __expf(-(half ? __ldg(bbet) : __ldg(bgam))));
    float om = 1.f - bl;
    const float* T = sT[half] + cc;
    float4 cb = __ldg((const float4*)((half ? cbb : cgb) + cc));
    float4 sp = __ldg((const float4*)((half ? sbb : sgb) + cc));
    float4 base;
    base.x = bl*cb.x + om*sp.x;
    base.y = bl*cb.y + om*sp.y;
    base.z = bl*cb.z + om*sp.z;
    base.w = bl*cb.w + om*sp.w;

    for (int px = warp; px < 256; px += 8) {
        float4 s = make_float4(0.f, 0.f, 0.f, 0.f);
        #pragma unroll
        for (int tp = 0; tp < 9; ++tp) {
            float4 v = *(const float4*)(T + sIdx[px][tp]);
            s.x += v.x; s.y += v.y; s.z += v.z; s.w += v.w;
        }
        float4 o;
        o.x = fmaf(bl, s.x, base.x);
        o.y = fmaf(bl, s.y, base.y);
        o.z = fmaf(bl, s.z, base.z);
        o.w = fmaf(bl, s.w, base.w);
        int y = y0 + (px >> 7), x = px & 127;
        *(float4*)(g_pre + (((size_t)(b*128 + y))*128 + x)*128 + c128) = o;
    }
}

// ================= K4: fused HMMA conv + thin epilogue + denorm =================
#define ROWB    144
#define PXB     272
#define ACT_OFF 0
#define WOFF    141440       // 520*272
#define WSTG    18432
#define DYN_BYTES 196736     // WOFF + 3*WSTG
#define GBS     264

__global__ __launch_bounds__(512, 1) void final_kernel(
    const float* __restrict__ x_in,
    const float* __restrict__ bgam, const float* __restrict__ bbet,
    float* __restrict__ out)
{
    extern __shared__ char dsm[];
    uint32_t sb = smem_u32(dsm);
    float* sGB = (float*)dsm;        // [128 c][264] epilogue, aliases actv buffer

    int t = threadIdx.x, wid = t >> 5, lane = t & 31;
    int b = blockIdx.y, y0 = blockIdx.x * 2;
    int wm = wid >> 2, wn = wid & 3, g = lane >> 2, tg = lane & 3;

    // ldmatrix lane address bases
    int rowA = wm*32 + (lane & 7) + ((lane >> 3) & 1)*8;
    int kbA  = (lane >> 4)*16;
    uint32_t aBase = sb + WOFF + rowA*ROWB + kbA;
    int rB  = wn >> 1;
    int x0l = (wn & 1)*64 + (lane & 7) + ((lane >> 4) & 1)*8;
    int kbB = ((lane >> 3) & 1)*16;
    uint32_t bBase = sb + ACT_OFF + (uint32_t)(rB*130 + x0l)*PXB + kbB;

    // one-time actv staging: 4 halo rows x 130 px x 128 ch
    for (int i = t; i < 8320; i += 512) {
        int seg = i & 15, e = i >> 4;
        int srow = e / 130, pxh = e - srow*130;
        int gy = y0 + srow - 1, gx = pxh - 1;
        bool in = ((unsigned)gy < 128u) && ((unsigned)gx < 128u);
        size_t src = (((size_t)(b*128 + (in ? gy : 0)))*128 + (in ? gx : 0))*128 + seg*8;
        cpa16(sb + ACT_OFF + (uint32_t)e*PXB + seg*16, g_act + src, in ? 16u : 0u);
    }
    asm volatile("cp.async.commit_group;" ::: "memory");

    auto stageW = [&](int ws) {
        int slot = ws % 3, h = ws / 9, tap = ws % 9;
        for (int i = t; i < 1024; i += 512) {
            int row = i >> 3, seg = i & 7;
            cpa16(sb + WOFF + slot*WSTG + row*ROWB + seg*16,
                  g_Aw + (size_t)tap*16384 + row*128 + h*64 + seg*8, 16);
        }
    };

    float acc[2][8][4];
    #pragma unroll
    for (int mt = 0; mt < 2; ++mt)
        #pragma unroll
        for (int nt = 0; nt < 8; ++nt)
            #pragma unroll
            for (int ci = 0; ci < 4; ++ci) acc[mt][nt][ci] = 0.f;

    stageW(0);
    asm volatile("cp.async.commit_group;" ::: "memory");
    stageW(1);
    asm volatile("cp.async.commit_group;" ::: "memory");

    for (int ws = 0; ws < 18; ++ws) {
        if (ws < 17) asm volatile("cp.async.wait_group 1;" ::: "memory");
        else         asm volatile("cp.async.wait_group 0;" ::: "memory");
        __syncthreads();
        if (ws < 16) {
            stageW(ws + 2);
            asm volatile("cp.async.commit_group;" ::: "memory");
        }

        int h = ws / 9, tap = ws % 9;
        int dy = tap / 3, dx = tap - 3*dy;
        uint32_t so = (uint32_t)(ws % 3)*WSTG;
        uint32_t bTap = bBase + (uint32_t)(dy*130 + dx)*PXB + h*128;

        #pragma unroll
        for (int kh = 0; kh < 4; ++kh) {
            uint32_t ah[2][4], bh[4][4];
            ldsm4(ah[0], aBase + so + kh*32);
            ldsm4(ah[1], aBase + so + kh*32 + 16*ROWB);
            #pragma unroll
            for (int q = 0; q < 4; ++q)
                ldsm4(bh[q], bTap + kh*32 + q*16*PXB);
            #pragma unroll
            for (int q = 0; q < 4; ++q)
                #pragma unroll
                for (int hf = 0; hf < 2; ++hf) {
                    int nt = 2*q + hf;
                    const uint32_t* bp = &bh[q][hf*2];
                    #pragma unroll
                    for (int mt = 0; mt < 2; ++mt)
                        mma_bf16(acc[mt][nt], ah[mt], bp);
                }
        }
    }
    __syncthreads();   // all actv/weight reads done before sGB overwrites

    // ---- thin epilogue: pre + (1-blend)*val into sGB ----
    float ga = 1.f / (1.f + __expf(-__ldg(bgam)));
    float ba = 1.f / (1.f + __expf(-__ldg(bbet)));

    #pragma unroll
    for (int mt = 0; mt < 2; ++mt)
        #pragma unroll
        for (int hi = 0; hi < 2; ++hi) {
            int m = wm*32 + mt*16 + g + hi*8;
            float om = (m < 64) ? (1.f - ga) : (1.f - ba);
            #pragma unroll
            for (int nt = 0; nt < 8; ++nt)
                #pragma unroll
                for (int lo = 0; lo < 2; ++lo) {
                    int px = wn*64 + nt*8 + tg*2 + lo;
                    int y = y0 + (px >> 7), x = px & 127;
                    float pre = __ldg(&g_pre[(((size_t)(b*128 + y))*128 + x)*128 + m]);
                    sGB[m*GBS + px] = fmaf(om, acc[mt][nt][hi*2 + lo], pre);
                }
        }
    __syncthreads();

    // ---- combine with instance-normed x (coalesced) ----
    for (int idx = t; idx < 16384; idx += 512) {
        int c = idx >> 8, p = idx & 255;
        int r = p >> 7, x = p & 127, y = y0 + r;
        int ch = (b << 6) + c;
        float xv = x_in[((size_t)ch << 14) + (y << 7) + x];
        float xn = (xv - __ldg(&g_mean[ch])) * __ldg(&g_rsig[ch]);
        float gf = sGB[c*GBS + p];
        float bf = sGB[(c + 64)*GBS + p];
        out[((size_t)ch << 14) + (y << 7) + x] = fmaf(xn, gf, xn) + bf;
    }
}

// ---------------- launch ----------------
extern "C" void kernel_launch(void* const* d_in, const int* in_sizes, int n_in,
                              void* d_out, int out_size) {
    const float* x      = (const float*)d_in[0];
    const float* segmap = (const float*)d_in[1];
    const float* codes  = (const float*)d_in[2];
    const float* mask   = (const float*)d_in[3];
    const float* fc_w   = (const float*)d_in[4];
    const float* fc_b   = (const float*)d_in[5];
    const float* cgw    = (const float*)d_in[6];
    const float* cgb    = (const float*)d_in[7];
    const float* cbw    = (const float*)d_in[8];
    const float* cbb    = (const float*)d_in[9];
    const float* ssw    = (const float*)d_in[10];
    const float* ssb    = (const float*)d_in[11];
    const float* sgw    = (const float*)d_in[12];
    const float* sgb    = (const float*)d_in[13];
    const float* sbw    = (const float*)d_in[14];
    const float* sbb    = (const float*)d_in[15];
    const float* bgam   = (const float*)d_in[16];
    const float* bbet   = (const float*)d_in[17];
    float* out = (float*)d_out;

    cudaFuncSetAttribute(final_kernel, cudaFuncAttributeMaxDynamicSharedMemorySize, DYN_BYTES);

    prep_all<<<4416, 256>>>(codes, fc_w, fc_b, segmap, x, sgw, sbw, mask, ssw, ssb);
    table_kernel<<<128, 256>>>(cgw, cbw);
    gather_kernel<<<256, 256>>>(cgb, cbb, sgb, sbb, bgam, bbet);
    {
        dim3 g(64, 4);
        final_kernel<<<g, 512, DYN_BYTES>>>(x, bgam, bbet, out);
    }
}

// round 14
// speedup vs baseline: 1.0473x; 1.0473x over previous
#include <cuda_runtime.h>
#include <cuda_bf16.h>
#include <math.h>
#include <stdint.h>

#define B_  4
#define C_  64
#define HH  128
#define WW  128
#define F_  5
#define L_  512
#define NH_ 128

// ---------------- device scratch ----------------
__device__ float g_mu[B_*F_*L_];
__device__ unsigned char g_rmap[B_*HH*WW];
__device__ float g_Tg[B_*9*F_*C_];               // [b][tap][f][c]
__device__ float g_Tb[B_*9*F_*C_];
__device__ __nv_bfloat16 g_act[(size_t)B_*HH*WW*NH_];  // NHWC bf16
__device__ __nv_bfloat16 g_Aw[9*128*128];        // [tap][c128][nh] bf16
__device__ float g_mean[B_*C_];
__device__ float g_rsig[B_*C_];
__device__ float g_pre[(size_t)B_*128*HH*WW];    // blended avg+biases, M-MAJOR [b][m][y][x]

// ---------------- helpers ----------------
__device__ __forceinline__ uint32_t smem_u32(const void* p) {
    uint32_t a;
    asm("{ .reg .u64 t; cvta.to.shared.u64 t, %1; cvt.u32.u64 %0, t; }" : "=r"(a) : "l"(p));
    return a;
}
__device__ __forceinline__ void cpa16(uint32_t dst, const void* src, uint32_t ssz) {
    asm volatile("cp.async.ca.shared.global [%0], [%1], 16, %2;"
                 :: "r"(dst), "l"(src), "r"(ssz) : "memory");
}
__device__ __forceinline__ void ldsm4(uint32_t* r, uint32_t addr) {
    asm volatile("ldmatrix.sync.aligned.m8n8.x4.shared.b16 {%0,%1,%2,%3}, [%4];"
        : "=r"(r[0]), "=r"(r[1]), "=r"(r[2]), "=r"(r[3]) : "r"(addr));
}
__device__ __forceinline__ void mma_bf16(float* d, const uint32_t* a, const uint32_t* b) {
    asm volatile("mma.sync.aligned.m16n8k16.row.col.f32.bf16.bf16.f32 "
        "{%0,%1,%2,%3},{%4,%5,%6,%7},{%8,%9},{%0,%1,%2,%3};"
        : "+f"(d[0]), "+f"(d[1]), "+f"(d[2]), "+f"(d[3])
        : "r"(a[0]), "r"(a[1]), "r"(a[2]), "r"(a[3]), "r"(b[0]), "r"(b[1]));
}

// ================= K1: all independent preps (mu | region | stats | wprep | sconv) =====
// grid 4416 x 256
__global__ void prep_all(const float* __restrict__ codes,
                         const float* __restrict__ fc_w,
                         const float* __restrict__ fc_b,
                         const float* __restrict__ seg,
                         const float* __restrict__ x,
                         const float* __restrict__ sgw,
                         const float* __restrict__ sbw,
                         const float* __restrict__ mask,
                         const float* __restrict__ ssw,
                         const float* __restrict__ ssb) {
    __shared__ float sh1[256], sh2[256];
    __shared__ float sw[NH_*27];
    __shared__ float smk[3][3][34];
    int bid = blockIdx.x, t = threadIdx.x;
    if (bid < 1280) {
        // mu: warp per output
        int gw = bid*8 + (t >> 5);
        int lane = t & 31;
        int bf = gw >> 9, k = gw & 511;
        int f = bf % F_;
        const float4* wp = (const float4*)(fc_w + ((size_t)f*L_ + k)*L_);
        const float4* cp = (const float4*)(codes + (size_t)bf*L_);
        float s = 0.f;
        #pragma unroll
        for (int i = 0; i < 4; ++i) {
            float4 w4 = wp[lane + i*32];
            float4 c4 = cp[lane + i*32];
            s = fmaf(w4.x, c4.x, fmaf(w4.y, c4.y, fmaf(w4.z, c4.z, fmaf(w4.w, c4.w, s))));
        }
        #pragma unroll
        for (int o = 16; o > 0; o >>= 1) s += __shfl_down_sync(0xffffffffu, s, o);
        if (lane == 0)
            g_mu[bf*L_ + k] = fmaxf(s + fc_b[f*L_ + k], 0.f);
    } else if (bid < 1536) {
        int p = (bid - 1280)*256 + t;
        int b = p >> 14, pix = p & 16383;
        int r = 5;
        #pragma unroll
        for (int j = 0; j < F_; ++j)
            if (seg[(b*F_ + j)*16384 + pix] > 0.f) r = j;
        g_rmap[p] = (unsigned char)r;
    } else if (bid < 1792) {
        int bc = bid - 1536;
        const float4* p = (const float4*)(x + (size_t)bc*16384);
        float s = 0.f, s2 = 0.f;
        for (int i = t; i < 4096; i += 256) {
            float4 v = p[i];
            s += v.x + v.y + v.z + v.w;
            s2 = fmaf(v.x, v.x, fmaf(v.y, v.y, fmaf(v.z, v.z, fmaf(v.w, v.w, s2))));
        }
        sh1[t] = s; sh2[t] = s2;
        __syncthreads();
        for (int o = 128; o > 0; o >>= 1) {
            if (t < o) { sh1[t] += sh1[t+o]; sh2[t] += sh2[t+o]; }
            __syncthreads();
        }
        if (t == 0) {
            float m = sh1[0] * (1.f/16384.f);
            float var = sh2[0] * (1.f/16384.f) - m*m;
            g_mean[bc] = m;
            g_rsig[bc] = rsqrtf(var + 1e-5f);
        }
    } else if (bid < 2368) {
        int idx = (bid - 1792)*256 + t;
        int nh = idx & 127, c = (idx >> 7) & 127, tap = idx >> 14;
        const float* src = (c < 64) ? sgw : sbw;
        float v = src[(((c & 63)*128) + nh)*9 + tap];
        g_Aw[idx] = __float2bfloat16_rn(v);
    } else {
        // sconv: mask(3) -> actv(128) bf16 NHWC
        int v = bid - 2368;
        int xblk = v & 3, y = (v >> 2) & 127, b = v >> 9;
        int x0 = xblk*32;
        for (int i = t; i < NH_*27; i += 256) sw[i] = ssw[i];
        for (int i = t; i < 3*3*34; i += 256) {
            int ch = i / 102, rem = i - ch*102;
            int r = rem / 34, cx = rem - r*34;
            int gy = y + r - 1, gx = x0 + cx - 1;
            float vv = 0.f;
            if ((unsigned)gy < 128u && (unsigned)gx < 128u)
                vv = mask[((b*3 + ch) << 14) + (gy << 7) + gx];
            smk[ch][r][cx] = vv;
        }
        __syncthreads();
        int px = t >> 3, g = t & 7;
        float mv[3][3][3];
        #pragma unroll
        for (int ch = 0; ch < 3; ++ch)
            #pragma unroll
            for (int r = 0; r < 3; ++r)
                #pragma unroll
                for (int d = 0; d < 3; ++d)
                    mv[ch][r][d] = smk[ch][r][px + d];
        int nh0 = g*16;
        unsigned hw[8];
        #pragma unroll 2
        for (int k = 0; k < 16; ++k) {
            int nh = nh0 + k;
            float acc = __ldg(&ssb[nh]);
            const float* wp = &sw[nh*27];
            #pragma unroll
            for (int ch = 0; ch < 3; ++ch)
                #pragma unroll
                for (int r = 0; r < 3; ++r)
                    #pragma unroll
                    for (int d = 0; d < 3; ++d)
                        acc = fmaf(mv[ch][r][d], wp[ch*9 + r*3 + d], acc);
            acc = fmaxf(acc, 0.f);
            unsigned hb = (unsigned)__bfloat16_as_ushort(__float2bfloat16_rn(acc));
            if (k & 1) hw[k>>1] |= hb << 16;
            else       hw[k>>1]  = hb;
        }
        size_t base = (((size_t)(b*128 + y))*128 + (x0 + px))*128 + nh0;
        uint4* dh = (uint4*)&g_act[base];
        dh[0] = make_uint4(hw[0], hw[1], hw[2], hw[3]);
        dh[1] = make_uint4(hw[4], hw[5], hw[6], hw[7]);
    }
}

// ================= K2: tables (R12 v2: warp per (tbl,b,f,c), all 9 taps) =========
__global__ void table_kernel(const float* __restrict__ cgw,
                             const float* __restrict__ cbw) {
    int gw = blockIdx.x*8 + (threadIdx.x >> 5);
    int lane = threadIdx.x & 31;
    int tbl = gw / 1280;  int r = gw - tbl*1280;
    int b = r / 320;      int r2 = r - b*320;
    int f = r2 >> 6;      int c = r2 & 63;
    const float* wv = (tbl ? cbw : cgw) + (size_t)c*L_*9;
    const float* m = g_mu + (b*F_ + f)*L_;
    float s[9];
    #pragma unroll
    for (int tp = 0; tp < 9; ++tp) s[tp] = 0.f;
    for (int l = lane; l < L_; l += 32) {
        float mv = m[l];
        const float* wl = wv + l*9;
        #pragma unroll
        for (int tp = 0; tp < 9; ++tp) s[tp] = fmaf(wl[tp], mv, s[tp]);
    }
    #pragma unroll
    for (int tp = 0; tp < 9; ++tp) {
        float v = s[tp];
        #pragma unroll
        for (int o = 16; o > 0; o >>= 1) v += __shfl_down_sync(0xffffffffu, v, o);
        if (lane == 0)
            (tbl ? g_Tb : g_Tg)[((b*9 + tp)*F_ + f)*64 + c] = v;
    }
}

// ================= K3: gather v4 — m-major output, coalesced stores ==============
// grid 256 (b x 64 row-pairs), 256 thr. warp = 4-channel group, lane = pixel.
__global__ void gather_kernel(const float* __restrict__ cgb,
                              const float* __restrict__ cbb,
                              const float* __restrict__ sgb,
                              const float* __restrict__ sbb,
                              const float* __restrict__ bgam,
                              const float* __restrict__ bbet) {
    __shared__ float sT[2][54*68];       // [tbl][(tap*6+r)*68 + c]; r=5 row zero
    __shared__ unsigned short sIdx[256][10];
    int bid = blockIdx.x, t = threadIdx.x;
    int b = bid >> 6, y0 = (bid & 63)*2;

    for (int i = t; i < 54*64; i += 256) {
        int row = i >> 6, c = i & 63;
        int tp = row / 6, q = row - tp*6;
        float vg = 0.f, vb = 0.f;
        if (q < 5) {
            int src = b*2880 + (tp*5 + q)*64 + c;
            vg = g_Tg[src]; vb = g_Tb[src];
        }
        sT[0][row*68 + c] = vg;
        sT[1][row*68 + c] = vb;
    }
    // per-pixel tap indices (thread = pixel)
    {
        int y = y0 + (t >> 7), x = t & 127;
        #pragma unroll
        for (int tp = 0; tp < 9; ++tp) {
            int dy = tp / 3, dx = tp - 3*dy;
            int gy = y + dy - 1, gx = x + dx - 1;
            int rr = 5;
            if ((unsigned)gy < 128u && (unsigned)gx < 128u)
                rr = g_rmap[(b << 14) + (gy << 7) + gx];
            sIdx[t][tp] = (unsigned short)((tp*6 + rr)*68);
        }
    }
    __syncthreads();

    int warp = t >> 5, lane = t & 31;
    float blg = 1.f / (1.f + __expf(-__ldg(bgam)));
    float blb = 1.f / (1.f + __expf(-__ldg(bbet)));

    #pragma unroll
    for (int cgi = 0; cgi < 4; ++cgi) {
        int cg = warp + cgi*8;          // 0..31
        int c128 = cg*4;
        int half = c128 >> 6;
        int cc = c128 & 63;
        float bl = half ? blb : blg;
        float om = 1.f - bl;
        const float* T = sT[half] + cc;
        float4 cb = __ldg((const float4*)((half ? cbb : cgb) + cc));
        float4 sp = __ldg((const float4*)((half ? sbb : sgb) + cc));
        float4 base;
        base.x = bl*cb.x + om*sp.x;
        base.y = bl*cb.y + om*sp.y;
        base.z = bl*cb.z + om*sp.z;
        base.w = bl*cb.w + om*sp.w;

        #pragma unroll 2
        for (int pxi = 0; pxi < 8; ++pxi) {
            int px = pxi*32 + lane;
            float4 s = make_float4(0.f, 0.f, 0.f, 0.f);
            #pragma unroll
            for (int tp = 0; tp < 9; ++tp) {
                float4 v = *(const float4*)(T + sIdx[px][tp]);
                s.x += v.x; s.y += v.y; s.z += v.z; s.w += v.w;
            }
            int y = y0 + (px >> 7), x = px & 127;
            size_t pbase = (((size_t)(b*128 + c128)) << 14) + (y << 7) + x;
            g_pre[pbase]           = fmaf(bl, s.x, base.x);
            g_pre[pbase + 16384]   = fmaf(bl, s.y, base.y);
            g_pre[pbase + 2*16384] = fmaf(bl, s.z, base.z);
            g_pre[pbase + 3*16384] = fmaf(bl, s.w, base.w);
        }
    }
}

// ================= K4: fused HMMA conv + thin epilogue + denorm =================
#define ROWB    144
#define PXB     272
#define ACT_OFF 0
#define WOFF    141440       // 520*272
#define WSTG    18432
#define DYN_BYTES 196736     // WOFF + 3*WSTG
#define GBS     264

__global__ __launch_bounds__(512, 1) void final_kernel(
    const float* __restrict__ x_in,
    const float* __restrict__ bgam, const float* __restrict__ bbet,
    float* __restrict__ out)
{
    extern __shared__ char dsm[];
    uint32_t sb = smem_u32(dsm);
    float* sGB = (float*)dsm;        // [128 c][264] epilogue, aliases actv buffer

    int t = threadIdx.x, wid = t >> 5, lane = t & 31;
    int b = blockIdx.y, y0 = blockIdx.x * 2;
    int wm = wid >> 2, wn = wid & 3, g = lane >> 2, tg = lane & 3;

    // ldmatrix lane address bases
    int rowA = wm*32 + (lane & 7) + ((lane >> 3) & 1)*8;
    int kbA  = (lane >> 4)*16;
    uint32_t aBase = sb + WOFF + rowA*ROWB + kbA;
    int rB  = wn >> 1;
    int x0l = (wn & 1)*64 + (lane & 7) + ((lane >> 4) & 1)*8;
    int kbB = ((lane >> 3) & 1)*16;
    uint32_t bBase = sb + ACT_OFF + (uint32_t)(rB*130 + x0l)*PXB + kbB;

    // one-time actv staging: 4 halo rows x 130 px x 128 ch
    for (int i = t; i < 8320; i += 512) {
        int seg = i & 15, e = i >> 4;
        int srow = e / 130, pxh = e - srow*130;
        int gy = y0 + srow - 1, gx = pxh - 1;
        bool in = ((unsigned)gy < 128u) && ((unsigned)gx < 128u);
        size_t src = (((size_t)(b*128 + (in ? gy : 0)))*128 + (in ? gx : 0))*128 + seg*8;
        cpa16(sb + ACT_OFF + (uint32_t)e*PXB + seg*16, g_act + src, in ? 16u : 0u);
    }
    asm volatile("cp.async.commit_group;" ::: "memory");

    auto stageW = [&](int ws) {
        int slot = ws % 3, h = ws / 9, tap = ws % 9;
        for (int i = t; i < 1024; i += 512) {
            int row = i >> 3, seg = i & 7;
            cpa16(sb + WOFF + slot*WSTG + row*ROWB + seg*16,
                  g_Aw + (size_t)tap*16384 + row*128 + h*64 + seg*8, 16);
        }
    };

    float acc[2][8][4];
    #pragma unroll
    for (int mt = 0; mt < 2; ++mt)
        #pragma unroll
        for (int nt = 0; nt < 8; ++nt)
            #pragma unroll
            for (int ci = 0; ci < 4; ++ci) acc[mt][nt][ci] = 0.f;

    stageW(0);
    asm volatile("cp.async.commit_group;" ::: "memory");
    stageW(1);
    asm volatile("cp.async.commit_group;" ::: "memory");

    for (int ws = 0; ws < 18; ++ws) {
        if (ws < 17) asm volatile("cp.async.wait_group 1;" ::: "memory");
        else         asm volatile("cp.async.wait_group 0;" ::: "memory");
        __syncthreads();
        if (ws < 16) {
            stageW(ws + 2);
            asm volatile("cp.async.commit_group;" ::: "memory");
        }

        int h = ws / 9, tap = ws % 9;
        int dy = tap / 3, dx = tap - 3*dy;
        uint32_t so = (uint32_t)(ws % 3)*WSTG;
        uint32_t bTap = bBase + (uint32_t)(dy*130 + dx)*PXB + h*128;

        #pragma unroll
        for (int kh = 0; kh < 4; ++kh) {
            uint32_t ah[2][4], bh[4][4];
            ldsm4(ah[0], aBase + so + kh*32);
            ldsm4(ah[1], aBase + so + kh*32 + 16*ROWB);
            #pragma unroll
            for (int q = 0; q < 4; ++q)
                ldsm4(bh[q], bTap + kh*32 + q*16*PXB);
            #pragma unroll
            for (int q = 0; q < 4; ++q)
                #pragma unroll
                for (int hf = 0; hf < 2; ++hf) {
                    int nt = 2*q + hf;
                    const uint32_t* bp = &bh[q][hf*2];
                    #pragma unroll
                    for (int mt = 0; mt < 2; ++mt)
                        mma_bf16(acc[mt][nt], ah[mt], bp);
                }
        }
    }
    __syncthreads();   // all actv/weight reads done before sGB overwrites

    // ---- thin epilogue: om*val only, no global loads ----
    float ga = 1.f / (1.f + __expf(-__ldg(bgam)));
    float ba = 1.f / (1.f + __expf(-__ldg(bbet)));

    #pragma unroll
    for (int mt = 0; mt < 2; ++mt)
        #pragma unroll
        for (int hi = 0; hi < 2; ++hi) {
            int m = wm*32 + mt*16 + g + hi*8;
            float om = (m < 64) ? (1.f - ga) : (1.f - ba);
            #pragma unroll
            for (int nt = 0; nt < 8; ++nt)
                #pragma unroll
                for (int lo = 0; lo < 2; ++lo) {
                    int px = wn*64 + nt*8 + tg*2 + lo;
                    sGB[m*GBS + px] = om * acc[mt][nt][hi*2 + lo];
                }
        }
    __syncthreads();

    // ---- combine with g_pre (m-major, coalesced) + instance-normed x ----
    for (int idx = t; idx < 16384; idx += 512) {
        int c = idx >> 8, p = idx & 255;
        int r = p >> 7, x = p & 127, y = y0 + r;
        int ch = (b << 6) + c;
        size_t sp = ((size_t)y << 7) + x;
        float gf = sGB[c*GBS + p]
                 + __ldg(&g_pre[(((size_t)(b*128 + c)) << 14) + sp]);
        float bf = sGB[(c + 64)*GBS + p]
                 + __ldg(&g_pre[(((size_t)(b*128 + 64 + c)) << 14) + sp]);
        float xv = x_in[((size_t)ch << 14) + sp];
        float xn = (xv - __ldg(&g_mean[ch])) * __ldg(&g_rsig[ch]);
        out[((size_t)ch << 14) + sp] = fmaf(xn, gf, xn) + bf;
    }
}

// ---------------- launch ----------------
extern "C" void kernel_launch(void* const* d_in, const int* in_sizes, int n_in,
                              void* d_out, int out_size) {
    const float* x      = (const float*)d_in[0];
    const float* segmap = (const float*)d_in[1];
    const float* codes  = (const float*)d_in[2];
    const float* mask   = (const float*)d_in[3];
    const float* fc_w   = (const float*)d_in[4];
    const float* fc_b   = (const float*)d_in[5];
    const float* cgw    = (const float*)d_in[6];
    const float* cgb    = (const float*)d_in[7];
    const float* cbw    = (const float*)d_in[8];
    const float* cbb    = (const float*)d_in[9];
    const float* ssw    = (const float*)d_in[10];
    const float* ssb    = (const float*)d_in[11];
    const float* sgw    = (const float*)d_in[12];
    const float* sgb    = (const float*)d_in[13];
    const float* sbw    = (const float*)d_in[14];
    const float* sbb    = (const float*)d_in[15];
    const float* bgam   = (const float*)d_in[16];
    const float* bbet   = (const float*)d_in[17];
    float* out = (float*)d_out;

    cudaFuncSetAttribute(final_kernel, cudaFuncAttributeMaxDynamicSharedMemorySize, DYN_BYTES);

    prep_all<<<4416, 256>>>(codes, fc_w, fc_b, segmap, x, sgw, sbw, mask, ssw, ssb);
    table_kernel<<<320, 256>>>(cgw, cbw);
    gather_kernel<<<256, 256>>>(cgb, cbb, sgb, sbb, bgam, bbet);
    {
        dim3 g(64, 4);
        final_kernel<<<g, 512, DYN_BYTES>>>(x, bgam, bbet, out);
    }
}

// round 15
// speedup vs baseline: 1.1146x; 1.0643x over previous
#include <cuda_runtime.h>
#include <cuda_bf16.h>
#include <math.h>
#include <stdint.h>

#define B_  4
#define C_  64
#define HH  128
#define WW  128
#define F_  5
#define L_  512
#define NH_ 128

// ---------------- device scratch ----------------
__device__ float g_mu[B_*F_*L_];
__device__ unsigned char g_rmap[B_*HH*WW];
__device__ float g_Tg[B_*9*F_*C_];               // [b][tap][f][c]
__device__ float g_Tb[B_*9*F_*C_];
__device__ __nv_bfloat16 g_act[(size_t)B_*HH*WW*NH_];  // NHWC bf16
__device__ __nv_bfloat16 g_Aw[9*128*128];        // [tap][c128][nh] bf16
__device__ float g_mean[B_*C_];
__device__ float g_rsig[B_*C_];

// ---------------- helpers ----------------
__device__ __forceinline__ uint32_t smem_u32(const void* p) {
    uint32_t a;
    asm("{ .reg .u64 t; cvta.to.shared.u64 t, %1; cvt.u32.u64 %0, t; }" : "=r"(a) : "l"(p));
    return a;
}
__device__ __forceinline__ void cpa16(uint32_t dst, const void* src, uint32_t ssz) {
    asm volatile("cp.async.ca.shared.global [%0], [%1], 16, %2;"
                 :: "r"(dst), "l"(src), "r"(ssz) : "memory");
}
__device__ __forceinline__ void ldsm4(uint32_t* r, uint32_t addr) {
    asm volatile("ldmatrix.sync.aligned.m8n8.x4.shared.b16 {%0,%1,%2,%3}, [%4];"
        : "=r"(r[0]), "=r"(r[1]), "=r"(r[2]), "=r"(r[3]) : "r"(addr));
}
__device__ __forceinline__ void mma_bf16(float* d, const uint32_t* a, const uint32_t* b) {
    asm volatile("mma.sync.aligned.m16n8k16.row.col.f32.bf16.bf16.f32 "
        "{%0,%1,%2,%3},{%4,%5,%6,%7},{%8,%9},{%0,%1,%2,%3};"
        : "+f"(d[0]), "+f"(d[1]), "+f"(d[2]), "+f"(d[3])
        : "r"(a[0]), "r"(a[1]), "r"(a[2]), "r"(a[3]), "r"(b[0]), "r"(b[1]));
}

// ================= K1: all independent preps (mu | region | stats | wprep | sconv) =====
// grid 4416 x 256
__global__ void prep_all(const float* __restrict__ codes,
                         const float* __restrict__ fc_w,
                         const float* __restrict__ fc_b,
                         const float* __restrict__ seg,
                         const float* __restrict__ x,
                         const float* __restrict__ sgw,
                         const float* __restrict__ sbw,
                         const float* __restrict__ mask,
                         const float* __restrict__ ssw,
                         const float* __restrict__ ssb) {
    __shared__ float sh1[256], sh2[256];
    __shared__ float sw[NH_*27];
    __shared__ float smk[3][3][34];
    int bid = blockIdx.x, t = threadIdx.x;
    if (bid < 1280) {
        // mu: warp per output
        int gw = bid*8 + (t >> 5);
        int lane = t & 31;
        int bf = gw >> 9, k = gw & 511;
        int f = bf % F_;
        const float4* wp = (const float4*)(fc_w + ((size_t)f*L_ + k)*L_);
        const float4* cp = (const float4*)(codes + (size_t)bf*L_);
        float s = 0.f;
        #pragma unroll
        for (int i = 0; i < 4; ++i) {
            float4 w4 = wp[lane + i*32];
            float4 c4 = cp[lane + i*32];
            s = fmaf(w4.x, c4.x, fmaf(w4.y, c4.y, fmaf(w4.z, c4.z, fmaf(w4.w, c4.w, s))));
        }
        #pragma unroll
        for (int o = 16; o > 0; o >>= 1) s += __shfl_down_sync(0xffffffffu, s, o);
        if (lane == 0)
            g_mu[bf*L_ + k] = fmaxf(s + fc_b[f*L_ + k], 0.f);
    } else if (bid < 1536) {
        int p = (bid - 1280)*256 + t;
        int b = p >> 14, pix = p & 16383;
        int r = 5;
        #pragma unroll
        for (int j = 0; j < F_; ++j)
            if (seg[(b*F_ + j)*16384 + pix] > 0.f) r = j;
        g_rmap[p] = (unsigned char)r;
    } else if (bid < 1792) {
        int bc = bid - 1536;
        const float4* p = (const float4*)(x + (size_t)bc*16384);
        float s = 0.f, s2 = 0.f;
        for (int i = t; i < 4096; i += 256) {
            float4 v = p[i];
            s += v.x + v.y + v.z + v.w;
            s2 = fmaf(v.x, v.x, fmaf(v.y, v.y, fmaf(v.z, v.z, fmaf(v.w, v.w, s2))));
        }
        sh1[t] = s; sh2[t] = s2;
        __syncthreads();
        for (int o = 128; o > 0; o >>= 1) {
            if (t < o) { sh1[t] += sh1[t+o]; sh2[t] += sh2[t+o]; }
            __syncthreads();
        }
        if (t == 0) {
            float m = sh1[0] * (1.f/16384.f);
            float var = sh2[0] * (1.f/16384.f) - m*m;
            g_mean[bc] = m;
            g_rsig[bc] = rsqrtf(var + 1e-5f);
        }
    } else if (bid < 2368) {
        int idx = (bid - 1792)*256 + t;
        int nh = idx & 127, c = (idx >> 7) & 127, tap = idx >> 14;
        const float* src = (c < 64) ? sgw : sbw;
        float v = src[(((c & 63)*128) + nh)*9 + tap];
        g_Aw[idx] = __float2bfloat16_rn(v);
    } else {
        // sconv: mask(3) -> actv(128) bf16 NHWC
        int v = bid - 2368;
        int xblk = v & 3, y = (v >> 2) & 127, b = v >> 9;
        int x0 = xblk*32;
        for (int i = t; i < NH_*27; i += 256) sw[i] = ssw[i];
        for (int i = t; i < 3*3*34; i += 256) {
            int ch = i / 102, rem = i - ch*102;
            int r = rem / 34, cx = rem - r*34;
            int gy = y + r - 1, gx = x0 + cx - 1;
            float vv = 0.f;
            if ((unsigned)gy < 128u && (unsigned)gx < 128u)
                vv = mask[((b*3 + ch) << 14) + (gy << 7) + gx];
            smk[ch][r][cx] = vv;
        }
        __syncthreads();
        int px = t >> 3, g = t & 7;
        float mv[3][3][3];
        #pragma unroll
        for (int ch = 0; ch < 3; ++ch)
            #pragma unroll
            for (int r = 0; r < 3; ++r)
                #pragma unroll
                for (int d = 0; d < 3; ++d)
                    mv[ch][r][d] = smk[ch][r][px + d];
        int nh0 = g*16;
        unsigned hw[8];
        #pragma unroll 2
        for (int k = 0; k < 16; ++k) {
            int nh = nh0 + k;
            float acc = __ldg(&ssb[nh]);
            const float* wp = &sw[nh*27];
            #pragma unroll
            for (int ch = 0; ch < 3; ++ch)
                #pragma unroll
                for (int r = 0; r < 3; ++r)
                    #pragma unroll
                    for (int d = 0; d < 3; ++d)
                        acc = fmaf(mv[ch][r][d], wp[ch*9 + r*3 + d], acc);
            acc = fmaxf(acc, 0.f);
            unsigned hb = (unsigned)__bfloat16_as_ushort(__float2bfloat16_rn(acc));
            if (k & 1) hw[k>>1] |= hb << 16;
            else       hw[k>>1]  = hb;
        }
        size_t base = (((size_t)(b*128 + y))*128 + (x0 + px))*128 + nh0;
        uint4* dh = (uint4*)&g_act[base];
        dh[0] = make_uint4(hw[0], hw[1], hw[2], hw[3]);
        dh[1] = make_uint4(hw[4], hw[5], hw[6], hw[7]);
    }
}

// ================= K2: tables (warp per (tbl,b,f,c), all 9 taps) =================
__global__ void table_kernel(const float* __restrict__ cgw,
                             const float* __restrict__ cbw) {
    int gw = blockIdx.x*8 + (threadIdx.x >> 5);
    int lane = threadIdx.x & 31;
    int tbl = gw / 1280;  int r = gw - tbl*1280;
    int b = r / 320;      int r2 = r - b*320;
    int f = r2 >> 6;      int c = r2 & 63;
    const float* wv = (tbl ? cbw : cgw) + (size_t)c*L_*9;
    const float* m = g_mu + (b*F_ + f)*L_;
    float s[9];
    #pragma unroll
    for (int tp = 0; tp < 9; ++tp) s[tp] = 0.f;
    for (int l = lane; l < L_; l += 32) {
        float mv = m[l];
        const float* wl = wv + l*9;
        #pragma unroll
        for (int tp = 0; tp < 9; ++tp) s[tp] = fmaf(wl[tp], mv, s[tp]);
    }
    #pragma unroll
    for (int tp = 0; tp < 9; ++tp) {
        float v = s[tp];
        #pragma unroll
        for (int o = 16; o > 0; o >>= 1) v += __shfl_down_sync(0xffffffffu, v, o);
        if (lane == 0)
            (tbl ? g_Tb : g_Tg)[((b*9 + tp)*F_ + f)*64 + c] = v;
    }
}

// ================= K3: fused HMMA conv + inline gather + blend + denorm =================
// block = 2 out rows (256 px), 512 thr (16 warps, 4M x 4N), M = 128 couts.
// Persistent actv buffer; weights 2-stage ring; tables (pre-scaled by blend) +
// per-pixel tap indices + bias terms staged in dedicated smem; gather inlined
// into the combine phase (fixed pixel per thread -> tap rows in registers).
#define ROWB    144
#define PXB     272
#define ACT_OFF 0
#define WOFF    141440          // 520*272
#define WSTG    18432
#define T_OFF   178304          // sT0 (54*68 f) | sT1 (54*68 f) = 29376 B
#define IDX_OFF 207680          // 256*10 u16 = 5120 B
#define CT_OFF  212800          // 128 f = 512 B
#define DYN_BYTES 213312
#define GBS     264

__global__ __launch_bounds__(512, 1) void final_kernel(
    const float* __restrict__ x_in,
    const float* __restrict__ cgb, const float* __restrict__ cbb,
    const float* __restrict__ sgb, const float* __restrict__ sbb,
    const float* __restrict__ bgam, const float* __restrict__ bbet,
    float* __restrict__ out)
{
    extern __shared__ char dsm[];
    uint32_t sb = smem_u32(dsm);
    float* sGB = (float*)dsm;                     // [128 c][264], aliases actv buffer
    float* sT0 = (float*)(dsm + T_OFF);           // gamma table, pre-scaled by ga
    float* sT1 = sT0 + 54*68;                     // beta table, pre-scaled by ba
    unsigned short* sIdx = (unsigned short*)(dsm + IDX_OFF);  // [256][10]
    float* sCt = (float*)(dsm + CT_OFF);          // [128] bl*cbias + (1-bl)*spbias

    int t = threadIdx.x, wid = t >> 5, lane = t & 31;
    int b = blockIdx.y, y0 = blockIdx.x * 2;
    int wm = wid >> 2, wn = wid & 3, g = lane >> 2, tg = lane & 3;

    float ga = 1.f / (1.f + __expf(-__ldg(bgam)));
    float ba = 1.f / (1.f + __expf(-__ldg(bbet)));

    // ldmatrix lane address bases
    int rowA = wm*32 + (lane & 7) + ((lane >> 3) & 1)*8;
    int kbA  = (lane >> 4)*16;
    uint32_t aBase = sb + WOFF + rowA*ROWB + kbA;
    int rB  = wn >> 1;
    int x0l = (wn & 1)*64 + (lane & 7) + ((lane >> 4) & 1)*8;
    int kbB = ((lane >> 3) & 1)*16;
    uint32_t bBase = sb + ACT_OFF + (uint32_t)(rB*130 + x0l)*PXB + kbB;

    // one-time actv staging: 4 halo rows x 130 px x 128 ch
    for (int i = t; i < 8320; i += 512) {
        int seg = i & 15, e = i >> 4;
        int srow = e / 130, pxh = e - srow*130;
        int gy = y0 + srow - 1, gx = pxh - 1;
        bool in = ((unsigned)gy < 128u) && ((unsigned)gx < 128u);
        size_t src = (((size_t)(b*128 + (in ? gy : 0)))*128 + (in ? gx : 0))*128 + seg*8;
        cpa16(sb + ACT_OFF + (uint32_t)e*PXB + seg*16, g_act + src, in ? 16u : 0u);
    }
    asm volatile("cp.async.commit_group;" ::: "memory");

    auto stageW = [&](int ws) {
        int slot = ws & 1, h = ws / 9, tap = ws % 9;
        for (int i = t; i < 1024; i += 512) {
            int row = i >> 3, seg = i & 7;
            cpa16(sb + WOFF + slot*WSTG + row*ROWB + seg*16,
                  g_Aw + (size_t)tap*16384 + row*128 + h*64 + seg*8, 16);
        }
    };
    stageW(0);
    asm volatile("cp.async.commit_group;" ::: "memory");

    // stage tables (pre-scaled), per-pixel tap rows, bias terms (plain STS,
    // regions untouched by cp.async)
    for (int i = t; i < 54*64; i += 512) {
        int row = i >> 6, c = i & 63;
        int tp = row / 6, q = row - tp*6;
        float vg = 0.f, vb = 0.f;
        if (q < 5) {
            int src = b*2880 + (tp*5 + q)*64 + c;
            vg = g_Tg[src]; vb = g_Tb[src];
        }
        sT0[row*68 + c] = ga * vg;
        sT1[row*68 + c] = ba * vb;
    }
    if (t < 256) {
        int y = y0 + (t >> 7), x = t & 127;
        #pragma unroll
        for (int tp = 0; tp < 9; ++tp) {
            int dy = tp / 3, dx = tp - 3*dy;
            int gy = y + dy - 1, gx = x + dx - 1;
            int rr = 5;
            if ((unsigned)gy < 128u && (unsigned)gx < 128u)
                rr = g_rmap[(b << 14) + (gy << 7) + gx];
            sIdx[t*10 + tp] = (unsigned short)((tp*6 + rr)*68);
        }
    }
    if (t < 128) {
        int half = t >> 6, c = t & 63;
        float bl = half ? ba : ga;
        float cb = __ldg(half ? &cbb[c] : &cgb[c]);
        float sp = __ldg(half ? &sbb[c] : &sgb[c]);
        sCt[t] = bl*cb + (1.f - bl)*sp;
    }

    float acc[2][8][4];
    #pragma unroll
    for (int mt = 0; mt < 2; ++mt)
        #pragma unroll
        for (int nt = 0; nt < 8; ++nt)
            #pragma unroll
            for (int ci = 0; ci < 4; ++ci) acc[mt][nt][ci] = 0.f;

    for (int ws = 0; ws < 18; ++ws) {
        asm volatile("cp.async.wait_group 0;" ::: "memory");
        __syncthreads();
        if (ws < 17) {
            stageW(ws + 1);
            asm volatile("cp.async.commit_group;" ::: "memory");
        }

        int h = ws / 9, tap = ws % 9;
        int dy = tap / 3, dx = tap - 3*dy;
        uint32_t so = (uint32_t)(ws & 1)*WSTG;
        uint32_t bTap = bBase + (uint32_t)(dy*130 + dx)*PXB + h*128;

        #pragma unroll
        for (int kh = 0; kh < 4; ++kh) {
            uint32_t ah[2][4], bh[4][4];
            ldsm4(ah[0], aBase + so + kh*32);
            ldsm4(ah[1], aBase + so + kh*32 + 16*ROWB);
            #pragma unroll
            for (int q = 0; q < 4; ++q)
                ldsm4(bh[q], bTap + kh*32 + q*16*PXB);
            #pragma unroll
            for (int q = 0; q < 4; ++q)
                #pragma unroll
                for (int hf = 0; hf < 2; ++hf) {
                    int nt = 2*q + hf;
                    const uint32_t* bp = &bh[q][hf*2];
                    #pragma unroll
                    for (int mt = 0; mt < 2; ++mt)
                        mma_bf16(acc[mt][nt], ah[mt], bp);
                }
        }
    }
    __syncthreads();   // all actv/weight reads done before sGB overwrites

    // ---- epilogue: om*val into sGB ----
    float omg = 1.f - ga, omb = 1.f - ba;
    #pragma unroll
    for (int mt = 0; mt < 2; ++mt)
        #pragma unroll
        for (int hi = 0; hi < 2; ++hi) {
            int m = wm*32 + mt*16 + g + hi*8;
            float om = (m < 64) ? omg : omb;
            #pragma unroll
            for (int nt = 0; nt < 8; ++nt)
                #pragma unroll
                for (int lo = 0; lo < 2; ++lo) {
                    int px = wn*64 + nt*8 + tg*2 + lo;
                    sGB[m*GBS + px] = om * acc[mt][nt][hi*2 + lo];
                }
        }
    __syncthreads();

    // ---- combine: inline gather (fixed pixel/thread) + instance norm ----
    {
        int p = t & 255, c0 = t >> 8;     // c = c0 + 2i covers all 64
        int y = y0 + (p >> 7), x = p & 127;
        size_t spo = ((size_t)y << 7) + x;
        int irow[9];
        #pragma unroll
        for (int tp = 0; tp < 9; ++tp) irow[tp] = sIdx[p*10 + tp];

        #pragma unroll 4
        for (int i = 0; i < 32; ++i) {
            int c = c0 + 2*i;
            float S0 = 0.f, S1 = 0.f;
            #pragma unroll
            for (int tp = 0; tp < 9; ++tp) {
                S0 += sT0[irow[tp] + c];
                S1 += sT1[irow[tp] + c];
            }
            float gf = sGB[c*GBS + p] + sCt[c] + S0;
            float bf = sGB[(c + 64)*GBS + p] + sCt[64 + c] + S1;
            int ch = (b << 6) + c;
            float xv = x_in[((size_t)ch << 14) + spo];
            float xn = (xv - __ldg(&g_mean[ch])) * __ldg(&g_rsig[ch]);
            out[((size_t)ch << 14) + spo] = fmaf(xn, gf, xn) + bf;
        }
    }
}

// ---------------- launch ----------------
extern "C" void kernel_launch(void* const* d_in, const int* in_sizes, int n_in,
                              void* d_out, int out_size) {
    const float* x      = (const float*)d_in[0];
    const float* segmap = (const float*)d_in[1];
    const float* codes  = (const float*)d_in[2];
    const float* mask   = (const float*)d_in[3];
    const float* fc_w   = (const float*)d_in[4];
    const float* fc_b   = (const float*)d_in[5];
    const float* cgw    = (const float*)d_in[6];
    const float* cgb    = (const float*)d_in[7];
    const float* cbw    = (const float*)d_in[8];
    const float* cbb    = (const float*)d_in[9];
    const float* ssw    = (const float*)d_in[10];
    const float* ssb    = (const float*)d_in[11];
    const float* sgw    = (const float*)d_in[12];
    const float* sgb    = (const float*)d_in[13];
    const float* sbw    = (const float*)d_in[14];
    const float* sbb    = (const float*)d_in[15];
    const float* bgam   = (const float*)d_in[16];
    const float* bbet   = (const float*)d_in[17];
    float* out = (float*)d_out;

    cudaFuncSetAttribute(final_kernel, cudaFuncAttributeMaxDynamicSharedMemorySize, DYN_BYTES);

    prep_all<<<4416, 256>>>(codes, fc_w, fc_b, segmap, x, sgw, sbw, mask, ssw, ssb);
    table_kernel<<<320, 256>>>(cgw, cbw);
    {
        dim3 g(64, 4);
        final_kernel<<<g, 512, DYN_BYTES>>>(x, cgb, cbb, sgb, sbb, bgam, bbet, out);
    }
}

// round 16
// speedup vs baseline: 1.9077x; 1.7116x over previous
#include <cuda_runtime.h>
#include <cuda_bf16.h>
#include <math.h>
#include <stdint.h>

#define B_  4
#define C_  64
#define HH  128
#define WW  128
#define F_  5
#define L_  512
#define NH_ 128

// ---------------- device scratch ----------------
__device__ float g_mu[B_*F_*L_];
__device__ unsigned char g_rmap[B_*HH*WW];
__device__ float g_Tg[B_*9*F_*C_];               // [b][tap][f][c]
__device__ float g_Tb[B_*9*F_*C_];
__device__ __nv_bfloat16 g_act[(size_t)B_*HH*WW*NH_];  // NHWC bf16
__device__ __nv_bfloat16 g_Aw[9*128*128];        // [tap][c128][nh] bf16
__device__ float g_mean[B_*C_];
__device__ float g_rsig[B_*C_];

// ---------------- helpers ----------------
__device__ __forceinline__ uint32_t smem_u32(const void* p) {
    uint32_t a;
    asm("{ .reg .u64 t; cvta.to.shared.u64 t, %1; cvt.u32.u64 %0, t; }" : "=r"(a) : "l"(p));
    return a;
}
__device__ __forceinline__ void cpa16(uint32_t dst, const void* src, uint32_t ssz) {
    asm volatile("cp.async.ca.shared.global [%0], [%1], 16, %2;"
                 :: "r"(dst), "l"(src), "r"(ssz) : "memory");
}
__device__ __forceinline__ void ldsm4(uint32_t* r, uint32_t addr) {
    asm volatile("ldmatrix.sync.aligned.m8n8.x4.shared.b16 {%0,%1,%2,%3}, [%4];"
        : "=r"(r[0]), "=r"(r[1]), "=r"(r[2]), "=r"(r[3]) : "r"(addr));
}
__device__ __forceinline__ void mma_bf16(float* d, const uint32_t* a, const uint32_t* b) {
    asm volatile("mma.sync.aligned.m16n8k16.row.col.f32.bf16.bf16.f32 "
        "{%0,%1,%2,%3},{%4,%5,%6,%7},{%8,%9},{%0,%1,%2,%3};"
        : "+f"(d[0]), "+f"(d[1]), "+f"(d[2]), "+f"(d[3])
        : "r"(a[0]), "r"(a[1]), "r"(a[2]), "r"(a[3]), "r"(b[0]), "r"(b[1]));
}

// ================= K1: all independent preps (mu | region | stats | wprep | sconv) =====
// grid 4416 x 256
__global__ void prep_all(const float* __restrict__ codes,
                         const float* __restrict__ fc_w,
                         const float* __restrict__ fc_b,
                         const float* __restrict__ seg,
                         const float* __restrict__ x,
                         const float* __restrict__ sgw,
                         const float* __restrict__ sbw,
                         const float* __restrict__ mask,
                         const float* __restrict__ ssw,
                         const float* __restrict__ ssb) {
    __shared__ float sh1[256], sh2[256];
    __shared__ float sw[NH_*27];
    __shared__ float smk[3][3][34];
    int bid = blockIdx.x, t = threadIdx.x;
    if (bid < 1280) {
        // mu: warp per output
        int gw = bid*8 + (t >> 5);
        int lane = t & 31;
        int bf = gw >> 9, k = gw & 511;
        int f = bf % F_;
        const float4* wp = (const float4*)(fc_w + ((size_t)f*L_ + k)*L_);
        const float4* cp = (const float4*)(codes + (size_t)bf*L_);
        float s = 0.f;
        #pragma unroll
        for (int i = 0; i < 4; ++i) {
            float4 w4 = wp[lane + i*32];
            float4 c4 = cp[lane + i*32];
            s = fmaf(w4.x, c4.x, fmaf(w4.y, c4.y, fmaf(w4.z, c4.z, fmaf(w4.w, c4.w, s))));
        }
        #pragma unroll
        for (int o = 16; o > 0; o >>= 1) s += __shfl_down_sync(0xffffffffu, s, o);
        if (lane == 0)
            g_mu[bf*L_ + k] = fmaxf(s + fc_b[f*L_ + k], 0.f);
    } else if (bid < 1536) {
        int p = (bid - 1280)*256 + t;
        int b = p >> 14, pix = p & 16383;
        int r = 5;
        #pragma unroll
        for (int j = 0; j < F_; ++j)
            if (seg[(b*F_ + j)*16384 + pix] > 0.f) r = j;
        g_rmap[p] = (unsigned char)r;
    } else if (bid < 1792) {
        int bc = bid - 1536;
        const float4* p = (const float4*)(x + (size_t)bc*16384);
        float s = 0.f, s2 = 0.f;
        for (int i = t; i < 4096; i += 256) {
            float4 v = p[i];
            s += v.x + v.y + v.z + v.w;
            s2 = fmaf(v.x, v.x, fmaf(v.y, v.y, fmaf(v.z, v.z, fmaf(v.w, v.w, s2))));
        }
        sh1[t] = s; sh2[t] = s2;
        __syncthreads();
        for (int o = 128; o > 0; o >>= 1) {
            if (t < o) { sh1[t] += sh1[t+o]; sh2[t] += sh2[t+o]; }
            __syncthreads();
        }
        if (t == 0) {
            float m = sh1[0] * (1.f/16384.f);
            float var = sh2[0] * (1.f/16384.f) - m*m;
            g_mean[bc] = m;
            g_rsig[bc] = rsqrtf(var + 1e-5f);
        }
    } else if (bid < 2368) {
        int idx = (bid - 1792)*256 + t;
        int nh = idx & 127, c = (idx >> 7) & 127, tap = idx >> 14;
        const float* src = (c < 64) ? sgw : sbw;
        float v = src[(((c & 63)*128) + nh)*9 + tap];
        g_Aw[idx] = __float2bfloat16_rn(v);
    } else {
        // sconv v2: thread = nh (conflict-free weight LDS), loop 16 pixels
        int v = bid - 2368;
        int xblk = v & 3, y = (v >> 2) & 127, b = v >> 9;
        int x0 = xblk*32;
        for (int i = t; i < NH_*27; i += 256) sw[i] = ssw[i];
        for (int i = t; i < 3*3*34; i += 256) {
            int ch = i / 102, rem = i - ch*102;
            int r = rem / 34, cx = rem - r*34;
            int gy = y + r - 1, gx = x0 + cx - 1;
            float vv = 0.f;
            if ((unsigned)gy < 128u && (unsigned)gx < 128u)
                vv = mask[((b*3 + ch) << 14) + (gy << 7) + gx];
            smk[ch][r][cx] = vv;
        }
        __syncthreads();
        int pg = t >> 7, nh = t & 127;
        float wr[27];
        #pragma unroll
        for (int j = 0; j < 27; ++j) wr[j] = sw[nh*27 + j];   // stride 27: bank-free
        float bias = __ldg(&ssb[nh]);
        #pragma unroll 4
        for (int k = 0; k < 16; ++k) {
            int px = pg*16 + k;
            float acc = bias;
            #pragma unroll
            for (int ch = 0; ch < 3; ++ch)
                #pragma unroll
                for (int r = 0; r < 3; ++r)
                    #pragma unroll
                    for (int d = 0; d < 3; ++d)
                        acc = fmaf(smk[ch][r][px + d], wr[ch*9 + r*3 + d], acc);
            acc = fmaxf(acc, 0.f);
            size_t base = (((size_t)(b*128 + y))*128 + (x0 + px))*128 + nh;
            g_act[base] = __float2bfloat16_rn(acc);
        }
    }
}

// ================= K2: tables (warp per (tbl,b,f,c), all 9 taps) =================
__global__ void table_kernel(const float* __restrict__ cgw,
                             const float* __restrict__ cbw) {
    int gw = blockIdx.x*8 + (threadIdx.x >> 5);
    int lane = threadIdx.x & 31;
    int tbl = gw / 1280;  int r = gw - tbl*1280;
    int b = r / 320;      int r2 = r - b*320;
    int f = r2 >> 6;      int c = r2 & 63;
    const float* wv = (tbl ? cbw : cgw) + (size_t)c*L_*9;
    const float* m = g_mu + (b*F_ + f)*L_;
    float s[9];
    #pragma unroll
    for (int tp = 0; tp < 9; ++tp) s[tp] = 0.f;
    for (int l = lane; l < L_; l += 32) {
        float mv = m[l];
        const float* wl = wv + l*9;
        #pragma unroll
        for (int tp = 0; tp < 9; ++tp) s[tp] = fmaf(wl[tp], mv, s[tp]);
    }
    #pragma unroll
    for (int tp = 0; tp < 9; ++tp) {
        float v = s[tp];
        #pragma unroll
        for (int o = 16; o > 0; o >>= 1) v += __shfl_down_sync(0xffffffffu, v, o);
        if (lane == 0)
            (tbl ? g_Tb : g_Tg)[((b*9 + tp)*F_ + f)*64 + c] = v;
    }
}

// ================= K3: fused HMMA conv + inline gather + blend + denorm =================
#define ROWB    144
#define PXB     272
#define ACT_OFF 0
#define WOFF    141440          // 520*272
#define WSTG    18432
#define T_OFF   178304          // sT0 (54*68 f) | sT1 (54*68 f) = 29376 B
#define IDX_OFF 207680          // 256*10 u16 = 5120 B
#define CT_OFF  212800          // 128 f = 512 B
#define DYN_BYTES 213312
#define GBS     264

__global__ __launch_bounds__(512, 1) void final_kernel(
    const float* __restrict__ x_in,
    const float* __restrict__ cgb, const float* __restrict__ cbb,
    const float* __restrict__ sgb, const float* __restrict__ sbb,
    const float* __restrict__ bgam, const float* __restrict__ bbet,
    float* __restrict__ out)
{
    extern __shared__ char dsm[];
    uint32_t sb = smem_u32(dsm);
    float* sGB = (float*)dsm;                     // [128 c][264], aliases actv buffer
    float* sT0 = (float*)(dsm + T_OFF);           // gamma table, pre-scaled by ga
    float* sT1 = sT0 + 54*68;                     // beta table, pre-scaled by ba
    unsigned short* sIdx = (unsigned short*)(dsm + IDX_OFF);  // [256][10]
    float* sCt = (float*)(dsm + CT_OFF);          // [128] bl*cbias + (1-bl)*spbias

    int t = threadIdx.x, wid = t >> 5, lane = t & 31;
    int b = blockIdx.y, y0 = blockIdx.x * 2;
    int wm = wid >> 2, wn = wid & 3, g = lane >> 2, tg = lane & 3;

    float ga = 1.f / (1.f + __expf(-__ldg(bgam)));
    float ba = 1.f / (1.f + __expf(-__ldg(bbet)));

    // ldmatrix lane address bases
    int rowA = wm*32 + (lane & 7) + ((lane >> 3) & 1)*8;
    int kbA  = (lane >> 4)*16;
    uint32_t aBase = sb + WOFF + rowA*ROWB + kbA;
    int rB  = wn >> 1;
    int x0l = (wn & 1)*64 + (lane & 7) + ((lane >> 4) & 1)*8;
    int kbB = ((lane >> 3) & 1)*16;
    uint32_t bBase = sb + ACT_OFF + (uint32_t)(rB*130 + x0l)*PXB + kbB;

    // one-time actv staging: 4 halo rows x 130 px x 128 ch
    for (int i = t; i < 8320; i += 512) {
        int seg = i & 15, e = i >> 4;
        int srow = e / 130, pxh = e - srow*130;
        int gy = y0 + srow - 1, gx = pxh - 1;
        bool in = ((unsigned)gy < 128u) && ((unsigned)gx < 128u);
        size_t src = (((size_t)(b*128 + (in ? gy : 0)))*128 + (in ? gx : 0))*128 + seg*8;
        cpa16(sb + ACT_OFF + (uint32_t)e*PXB + seg*16, g_act + src, in ? 16u : 0u);
    }
    asm volatile("cp.async.commit_group;" ::: "memory");

    auto stageW = [&](int ws) {
        int slot = ws & 1, h = ws / 9, tap = ws % 9;
        for (int i = t; i < 1024; i += 512) {
            int row = i >> 3, seg = i & 7;
            cpa16(sb + WOFF + slot*WSTG + row*ROWB + seg*16,
                  g_Aw + (size_t)tap*16384 + row*128 + h*64 + seg*8, 16);
        }
    };
    stageW(0);
    asm volatile("cp.async.commit_group;" ::: "memory");

    // stage tables (pre-scaled), per-pixel tap rows, bias terms
    for (int i = t; i < 54*64; i += 512) {
        int row = i >> 6, c = i & 63;
        int tp = row / 6, q = row - tp*6;
        float vg = 0.f, vb = 0.f;
        if (q < 5) {
            int src = b*2880 + (tp*5 + q)*64 + c;
            vg = g_Tg[src]; vb = g_Tb[src];
        }
        sT0[row*68 + c] = ga * vg;
        sT1[row*68 + c] = ba * vb;
    }
    if (t < 256) {
        int y = y0 + (t >> 7), x = t & 127;
        #pragma unroll
        for (int tp = 0; tp < 9; ++tp) {
            int dy = tp / 3, dx = tp - 3*dy;
            int gy = y + dy - 1, gx = x + dx - 1;
            int rr = 5;
            if ((unsigned)gy < 128u && (unsigned)gx < 128u)
                rr = g_rmap[(b << 14) + (gy << 7) + gx];
            sIdx[t*10 + tp] = (unsigned short)((tp*6 + rr)*68);
        }
    }
    if (t < 128) {
        int half = t >> 6, c = t & 63;
        float bl = half ? ba : ga;
        float cb = __ldg(half ? &cbb[c] : &cgb[c]);
        float sp = __ldg(half ? &sbb[c] : &sgb[c]);
        sCt[t] = bl*cb + (1.f - bl)*sp;
    }

    float acc[2][8][4];
    #pragma unroll
    for (int mt = 0; mt < 2; ++mt)
        #pragma unroll
        for (int nt = 0; nt < 8; ++nt)
            #pragma unroll
            for (int ci = 0; ci < 4; ++ci) acc[mt][nt][ci] = 0.f;

    for (int ws = 0; ws < 18; ++ws) {
        asm volatile("cp.async.wait_group 0;" ::: "memory");
        __syncthreads();
        if (ws < 17) {
            stageW(ws + 1);
            asm volatile("cp.async.commit_group;" ::: "memory");
        }

        int h = ws / 9, tap = ws % 9;
        int dy = tap / 3, dx = tap - 3*dy;
        uint32_t so = (uint32_t)(ws & 1)*WSTG;
        uint32_t bTap = bBase + (uint32_t)(dy*130 + dx)*PXB + h*128;

        #pragma unroll
        for (int kh = 0; kh < 4; ++kh) {
            uint32_t ah[2][4], bh[4][4];
            ldsm4(ah[0], aBase + so + kh*32);
            ldsm4(ah[1], aBase + so + kh*32 + 16*ROWB);
            #pragma unroll
            for (int q = 0; q < 4; ++q)
                ldsm4(bh[q], bTap + kh*32 + q*16*PXB);
            #pragma unroll
            for (int q = 0; q < 4; ++q)
                #pragma unroll
                for (int hf = 0; hf < 2; ++hf) {
                    int nt = 2*q + hf;
                    const uint32_t* bp = &bh[q][hf*2];
                    #pragma unroll
                    for (int mt = 0; mt < 2; ++mt)
                        mma_bf16(acc[mt][nt], ah[mt], bp);
                }
        }
    }
    __syncthreads();   // all actv/weight reads done before sGB overwrites

    // ---- epilogue: om*val into sGB ----
    float omg = 1.f - ga, omb = 1.f - ba;
    #pragma unroll
    for (int mt = 0; mt < 2; ++mt)
        #pragma unroll
        for (int hi = 0; hi < 2; ++hi) {
            int m = wm*32 + mt*16 + g + hi*8;
            float om = (m < 64) ? omg : omb;
            #pragma unroll
            for (int nt = 0; nt < 8; ++nt)
                #pragma unroll
                for (int lo = 0; lo < 2; ++lo) {
                    int px = wn*64 + nt*8 + tg*2 + lo;
                    sGB[m*GBS + px] = om * acc[mt][nt][hi*2 + lo];
                }
        }
    __syncthreads();

    // ---- combine: inline gather (fixed pixel/thread) + instance norm ----
    {
        int p = t & 255, c0 = t >> 8;     // c = c0 + 2i covers all 64
        int y = y0 + (p >> 7), x = p & 127;
        size_t spo = ((size_t)y << 7) + x;
        int irow[9];
        #pragma unroll
        for (int tp = 0; tp < 9; ++tp) irow[tp] = sIdx[p*10 + tp];

        #pragma unroll 4
        for (int i = 0; i < 32; ++i) {
            int c = c0 + 2*i;
            float S0 = 0.f, S1 = 0.f;
            #pragma unroll
            for (int tp = 0; tp < 9; ++tp) {
                S0 += sT0[irow[tp] + c];
                S1 += sT1[irow[tp] + c];
            }
            float gf = sGB[c*GBS + p] + sCt[c] + S0;
            float bf = sGB[(c + 64)*GBS + p] + sCt[64 + c] + S1;
            int ch = (b << 6) + c;
            float xv = x_in[((size_t)ch << 14) + spo];
            float xn = (xv - __ldg(&g_mean[ch])) * __ldg(&g_rsig[ch]);
            out[((size_t)ch << 14) + spo] = fmaf(xn, gf, xn) + bf;
        }
    }
}

// ---------------- launch ----------------
extern "C" void kernel_launch(void* const* d_in, const int* in_sizes, int n_in,
                              void* d_out, int out_size) {
    const float* x      = (const float*)d_in[0];
    const float* segmap = (const float*)d_in[1];
    const float* codes  = (const float*)d_in[2];
    const float* mask   = (const float*)d_in[3];
    const float* fc_w   = (const float*)d_in[4];
    const float* fc_b   = (const float*)d_in[5];
    const float* cgw    = (const float*)d_in[6];
    const float* cgb    = (const float*)d_in[7];
    const float* cbw    = (const float*)d_in[8];
    const float* cbb    = (const float*)d_in[9];
    const float* ssw    = (const float*)d_in[10];
    const float* ssb    = (const float*)d_in[11];
    const float* sgw    = (const float*)d_in[12];
    const float* sgb    = (const float*)d_in[13];
    const float* sbw    = (const float*)d_in[14];
    const float* sbb    = (const float*)d_in[15];
    const float* bgam   = (const float*)d_in[16];
    const float* bbet   = (const float*)d_in[17];
    float* out = (float*)d_out;

    cudaFuncSetAttribute(final_kernel, cudaFuncAttributeMaxDynamicSharedMemorySize, DYN_BYTES);

    prep_all<<<4416, 256>>>(codes, fc_w, fc_b, segmap, x, sgw, sbw, mask, ssw, ssb);
    table_kernel<<<320, 256>>>(cgw, cbw);
    {
        dim3 g(64, 4);
        final_kernel<<<g, 512, DYN_BYTES>>>(x, cgb, cbb, sgb, sbb, bgam, bbet, out);
    }
}